// round 15
// baseline (speedup 1.0000x reference)
#include <cuda_runtime.h>
#include <math.h>

#define IPB 8                       // images per CTA (one warp-pair each)
#define PWI 6996                    // floats/image: Xs 1156 + Qs 1156 + Ks 1156 + VsP 2304 + Ssc 1224
#define TABF 1904                   // dmask 4*17*20 + sin 272 + cos 272
#define SMEMF (IPB*PWI + TABF)

typedef unsigned long long u64;

// ---- packed weight buffer (k-pair interleaved: [k/2][col][2]) ----
#define OFF_PW   0                  // patch_w  [96][64][2]
#define OFF_WQ   12288              // Wq [8][32][64][2]
#define OFF_WK   45056              // Wk
#define OFF_WV   77824              // Wv [8][32][128][2]
#define OFF_WG   143360             // Wg
#define OFF_WO   208896             // Wo [8][64][64][2]
#define OFF_W1   274432             // w1 [8][32][12][2]
#define OFF_W2   280576             // w2 [8][6][64][2]
#define NPACK    286720

__device__ float WPbuf[NPACK];

__global__ void repack_kernel(const float* __restrict__ pw, const float* __restrict__ wq,
                              const float* __restrict__ wk, const float* __restrict__ wv,
                              const float* __restrict__ wg, const float* __restrict__ wo,
                              const float* __restrict__ w1, const float* __restrict__ w2) {
    int i = blockIdx.x * 256 + threadIdx.x;
    if (i >= NPACK) return;
    float v;
    if (i < OFF_WQ) {
        int f2 = i >> 7, r = i & 127, c = r >> 1, par = r & 1;
        v = pw[(f2 * 2 + par) * 64 + c];
    } else if (i < OFF_WK) {
        int j = i - OFF_WQ;
        int L = j >> 12, r = j & 4095, k2 = r >> 7, rr = r & 127, c = rr >> 1, par = rr & 1;
        v = wq[L * 4096 + (k2 * 2 + par) * 64 + c];
    } else if (i < OFF_WV) {
        int j = i - OFF_WK;
        int L = j >> 12, r = j & 4095, k2 = r >> 7, rr = r & 127, c = rr >> 1, par = rr & 1;
        v = wk[L * 4096 + (k2 * 2 + par) * 64 + c];
    } else if (i < OFF_WG) {
        int j = i - OFF_WV;
        int L = j >> 13, r = j & 8191, k2 = r >> 8, rr = r & 255, c = rr >> 1, par = rr & 1;
        v = wv[L * 8192 + (k2 * 2 + par) * 128 + c];
    } else if (i < OFF_WO) {
        int j = i - OFF_WG;
        int L = j >> 13, r = j & 8191, k2 = r >> 8, rr = r & 255, c = rr >> 1, par = rr & 1;
        v = wg[L * 8192 + (k2 * 2 + par) * 128 + c];
    } else if (i < OFF_W1) {
        int j = i - OFF_WO;
        int L = j >> 13, r = j & 8191, k2 = r >> 7, rr = r & 127, c = rr >> 1, par = rr & 1;
        v = wo[L * 8192 + (k2 * 2 + par) * 64 + c];
    } else if (i < OFF_W2) {
        int j = i - OFF_W1;
        int L = j / 768, r = j % 768, k2 = r / 24, rr = r % 24, c = rr >> 1, par = rr & 1;
        v = w1[L * 768 + (k2 * 2 + par) * 12 + c];
    } else {
        int j = i - OFF_W2;
        int L = j / 768, r = j % 768, k2 = r >> 7, rr = r & 127, c = rr >> 1, par = rr & 1;
        v = w2[L * 768 + (k2 * 2 + par) * 64 + c];
    }
    WPbuf[i] = v;
}

__device__ __forceinline__ void fma2(u64& d, u64 a, u64 b) {
    asm("fma.rn.f32x2 %0, %1, %2, %0;" : "+l"(d) : "l"(a), "l"(b));
}
__device__ __forceinline__ float hadd2(u64 a) {
    float lo, hi; asm("mov.b64 {%0, %1}, %2;" : "=f"(lo), "=f"(hi) : "l"(a));
    return lo + hi;
}
__device__ __forceinline__ float wsum(float v) {
#pragma unroll
    for (int d = 16; d > 0; d >>= 1) v += __shfl_xor_sync(0xffffffffu, v, d);
    return v;
}

__global__ void __launch_bounds__(512, 1) vit_kernel(
    const float* __restrict__ x,      const float* __restrict__ patch_b,
    const float* __restrict__ cls,    const float* __restrict__ pos,
    const float* __restrict__ ln1_s, const float* __restrict__ ln1_b,
    const float* __restrict__ b1,    const float* __restrict__ b2,
    const float* __restrict__ ln2_s, const float* __restrict__ ln2_b,
    const float* __restrict__ lnf_s, const float* __restrict__ lnf_b,
    const float* __restrict__ neck_w, const float* __restrict__ neck_b,
    const float* __restrict__ head_w, const float* __restrict__ head_b,
    float* __restrict__ out, int nimg)
{
    extern __shared__ float sm[];
    const int tid  = threadIdx.x;
    const int warp = tid >> 5, lane = tid & 31;
    const int pair = warp >> 1;
    const int wsel = warp & 1;           // 0: even tokens (incl cls), 1: odd tokens
    const int plane = (wsel << 5) | lane;
    const int barid = pair + 1;

#define PBAR() asm volatile("bar.sync %0, 64;" :: "r"(barid) : "memory")

    float* wb  = sm + pair * PWI;
    float* Xs  = wb;                // [17][68]  (patch staging [16][192] overlaps Xs/Qs/Ks)
    float* Qs  = wb + 1156;         // [17][68]  (reused: Gf[204], neck)
    float* Ks  = wb + 2312;         // [17][68]
    float* VsP = wb + 3468;         // [9][128][2] v pair-interleaved; reused as Gs[17][128]
    float* Ssc = wb + 5772;         // [68][18]  normalized scores, zero-padded
    float* tab = sm + IPB * PWI;
    float* DM = tab;                // [4][17][20]
    float* SN = tab + 1360;         // [17][16]
    float* CS = tab + 1632;         // [17][16]

    if (tid < 68) {
        int hh = tid / 17, n = tid % 17;
        float l0 = logf(1.0f / 32.0f), l1 = logf(1.0f / 512.0f);
        float gam = 1.0f - expf(l0 + (l1 - l0) * ((float)hh / 3.0f));
        float lg = logf(gam);
        float row[17]; float s = 0.f;
#pragma unroll
        for (int m = 0; m < 17; m++) {
            float v = (m <= n) ? expf(lg * (float)(n - m)) : 0.f;
            row[m] = v; s += v;
        }
        float nf = rsqrtf(s) * 0.25f;
#pragma unroll
        for (int m = 0; m < 17; m++) DM[(hh * 17 + n) * 20 + m] = row[m] * nf;
    }
    if (tid < 272) {
        int t = tid >> 4, j = tid & 15;
        float e = (float)(j >> 1) / 7.0f;
        float ang = expf(-e * logf(10000.0f));
        float a = (float)t * ang;
        SN[tid] = sinf(a); CS[tid] = cosf(a);
    }
    __syncthreads();

    const int col = lane * 2;       // lane's cols (D=64): {col, col+1}
    // V=128 col ownership: {col, col+1, 64+col, 64+col+1}

    for (int img = blockIdx.x * IPB + pair; img < nimg; img += gridDim.x * IPB) {
        // ================= patch embed (packed) =================
        const float* xi = x + (long)img * 3072;
        for (int i = plane; i < 3072; i += 64) {
            int c = i >> 10, rem = i & 1023, yy = rem >> 5, xx = rem & 31;
            int p = ((yy >> 3) << 2) + (xx >> 3);
            int f = (c << 6) + ((yy & 7) << 3) + (xx & 7);
            wb[p * 192 + f] = xi[i];          // staging [16][192] (f-contiguous)
        }
        PBAR();
        float2 h2[9];
        {
            u64 e0[8], e1[8];
#pragma unroll
            for (int j = 0; j < 8; j++) { e0[j] = 0ull; e1[j] = 0ull; }
            int pb0 = 1 - wsel;
#pragma unroll 1
            for (int f2 = 0; f2 < 96; f2++) {
                ulonglong2 wp = *(const ulonglong2*)(WPbuf + OFF_PW + f2 * 128 + col * 2);
#pragma unroll
                for (int j = 0; j < 8; j++) {
                    u64 xp = *(const u64*)(wb + (2 * j + pb0) * 192 + 2 * f2);
                    fma2(e0[j], xp, wp.x); fma2(e1[j], xp, wp.y);
                }
            }
            float2 pb = *(const float2*)(patch_b + col);
            if (wsel == 0) {
                float2 cl = *(const float2*)(cls + col);
                float2 p0 = *(const float2*)(pos + col);
                h2[0] = make_float2(cl.x + p0.x, cl.y + p0.y);
#pragma unroll
                for (int j = 0; j < 8; j++) {
                    int t = 2 + 2 * j;
                    float2 po = *(const float2*)(pos + t * 64 + col);
                    h2[1 + j] = make_float2(hadd2(e0[j]) + pb.x + po.x,
                                            hadd2(e1[j]) + pb.y + po.y);
                }
            } else {
#pragma unroll
                for (int j = 0; j < 8; j++) {
                    int t = 1 + 2 * j;
                    float2 po = *(const float2*)(pos + t * 64 + col);
                    h2[j] = make_float2(hadd2(e0[j]) + pb.x + po.x,
                                        hadd2(e1[j]) + pb.y + po.y);
                }
            }
        }
        PBAR();

        // ================= layers =================
#pragma unroll 1
        for (int L = 0; L < 8; L++) {
            // ---- LN1 -> Xs (own tokens) ----
            {
                float2 ls = *(const float2*)(ln1_s + L * 64 + col);
                float2 lb = *(const float2*)(ln1_b + L * 64 + col);
#pragma unroll
                for (int j = 0; j < 9; j++) {
                    int t = 2 * j + wsel;
                    if (t < 17) {
                        float s = wsum(h2[j].x + h2[j].y);
                        float q = wsum(h2[j].x * h2[j].x + h2[j].y * h2[j].y);
                        float mu = s * (1.0f / 64.0f);
                        float var = q * (1.0f / 64.0f) - mu * mu;
                        float r = rsqrtf(var + 1e-5f);
                        *(float2*)(Xs + t * 68 + col) =
                            make_float2((h2[j].x - mu) * r * ls.x + lb.x,
                                        (h2[j].y - mu) * r * ls.y + lb.y);
                    }
                }
            }
            PBAR();   // q/k reads ALL tokens' Xs

            // ---- q (warp0) / k (warp1): all 17 tokens in 2 halves, packed ----
            {
                const float* wsrc = WPbuf + (wsel ? OFF_WK : OFF_WQ) + L * 4096;
                float* dst = wsel ? Ks : Qs;
                int cc = col & 15;
#pragma unroll
                for (int half = 0; half < 2; half++) {
                    int t0 = half * 9;
                    int cnt = half ? 8 : 9;
                    u64 a0[9], a1[9];
#pragma unroll
                    for (int j = 0; j < 9; j++) { a0[j] = 0ull; a1[j] = 0ull; }
#pragma unroll 1
                    for (int k2 = 0; k2 < 32; k2++) {
                        ulonglong2 wp = *(const ulonglong2*)(wsrc + k2 * 128 + col * 2);
#pragma unroll
                        for (int j = 0; j < 9; j++) {
                            if (j < cnt) {
                                u64 xp = *(const u64*)(Xs + (t0 + j) * 68 + 2 * k2);
                                fma2(a0[j], xp, wp.x); fma2(a1[j], xp, wp.y);
                            }
                        }
                    }
#pragma unroll
                    for (int j = 0; j < 9; j++) {
                        if (j < cnt) {
                            int t = t0 + j;
                            float v0 = hadd2(a0[j]), v1 = hadd2(a1[j]);
                            float sn = SN[t * 16 + cc], cn = CS[t * 16 + cc];
                            *(float2*)(dst + t * 68 + col) =
                                make_float2(v0 * cn - v1 * sn, v1 * cn + v0 * sn);
                        }
                    }
                }
            }

            // ---- v (own tokens, 2 col passes) -> VsP pair-interleaved ----
#pragma unroll
            for (int pass = 0; pass < 2; pass++) {
                int cp = pass * 64 + col;
                u64 b0[9], b1[9];
#pragma unroll
                for (int j = 0; j < 9; j++) { b0[j] = 0ull; b1[j] = 0ull; }
#pragma unroll 2
                for (int k2 = 0; k2 < 32; k2++) {
                    ulonglong2 wp = *(const ulonglong2*)(WPbuf + OFF_WV + L * 8192 + k2 * 256 + cp * 2);
#pragma unroll
                    for (int j = 0; j < 9; j++) {
                        int t = 2 * j + wsel;
                        if (t < 17) {
                            u64 xp = *(const u64*)(Xs + t * 68 + 2 * k2);
                            fma2(b0[j], xp, wp.x); fma2(b1[j], xp, wp.y);
                        }
                    }
                }
#pragma unroll
                for (int j = 0; j < 9; j++) {
                    int t = 2 * j + wsel;
                    if (t < 17) {
                        VsP[(t >> 1) * 256 + cp * 2 + (t & 1)]       = hadd2(b0[j]);
                        VsP[(t >> 1) * 256 + (cp + 1) * 2 + (t & 1)] = hadd2(b1[j]);
                    } else {   // virtual token 17: zero-fill pair slots
                        VsP[8 * 256 + cp * 2 + 1]       = 0.f;
                        VsP[8 * 256 + (cp + 1) * 2 + 1] = 0.f;
                    }
                }
            }
            PBAR();   // Qs, Ks, VsP complete

            // ---- stage A: normalized scores -> Ssc[68][18] (zero-padded) ----
#pragma unroll 1
            for (int r = plane; r < 68; r += 64) {
                int hh = r & 3, n = r >> 2;
                const float* qp = Qs + n * 68 + hh * 16;
                float4 q0 = *(const float4*)(qp);
                float4 q1 = *(const float4*)(qp + 4);
                float4 q2 = *(const float4*)(qp + 8);
                float4 q3 = *(const float4*)(qp + 12);
                const float* dmr = DM + (hh * 17 + n) * 20;
                float sv[17]; float ssum = 0.f;
#pragma unroll
                for (int m = 0; m < 17; m++) {
                    if (m <= n) {
                        const float* kp = Ks + m * 68 + hh * 16;
                        float4 k0 = *(const float4*)(kp);
                        float4 k1 = *(const float4*)(kp + 4);
                        float4 k2 = *(const float4*)(kp + 8);
                        float4 k3 = *(const float4*)(kp + 12);
                        float s = q0.x*k0.x + q0.y*k0.y + q0.z*k0.z + q0.w*k0.w
                                + q1.x*k1.x + q1.y*k1.y + q1.z*k1.z + q1.w*k1.w
                                + q2.x*k2.x + q2.y*k2.y + q2.z*k2.z + q2.w*k2.w
                                + q3.x*k3.x + q3.y*k3.y + q3.z*k3.z + q3.w*k3.w;
                        s *= dmr[m];
                        sv[m] = s; ssum += s;
                    }
                }
                float den = fabsf(ssum); den = den > 1.f ? den : 1.f;
                float inv = 1.f / den;
                float* sp = Ssc + (hh * 17 + n) * 18;
#pragma unroll
                for (int m = 0; m < 17; m++) sp[m] = (m <= n) ? sv[m] * inv : 0.f;
                sp[17] = 0.f;
            }
            PBAR();   // Ssc complete

            // ---- stage B: o = S @ v (packed along m) + dual-head groupnorm ----
            float4 ov[9];
            {
                const float* spAb = Ssc + ((lane >> 4) * 17) * 18;
                const float* spBb = Ssc + (((lane >> 4) + 2) * 17) * 18;
#pragma unroll
                for (int j = 0; j < 9; j++) {
                    int n = 2 * j + wsel;
                    ov[j] = make_float4(0, 0, 0, 0);
                    if (n < 17) {
                        const float* spA = spAb + n * 18;
                        const float* spB = spBb + n * 18;
                        u64 oA0 = 0ull, oA1 = 0ull, oB0 = 0ull, oB1 = 0ull;
#pragma unroll 1
                        for (int m2 = 0; m2 <= (n >> 1); m2++) {
                            u64 sA = *(const u64*)(spA + 2 * m2);
                            u64 sB = *(const u64*)(spB + 2 * m2);
                            ulonglong2 lo = *(const ulonglong2*)(VsP + m2 * 256 + (lane << 2));
                            ulonglong2 hi = *(const ulonglong2*)(VsP + m2 * 256 + 128 + (lane << 2));
                            fma2(oA0, sA, lo.x); fma2(oA1, sA, lo.y);
                            fma2(oB0, sB, hi.x); fma2(oB1, sB, hi.y);
                        }
                        float xA0 = hadd2(oA0), xA1 = hadd2(oA1);
                        float xB0 = hadd2(oB0), xB1 = hadd2(oB1);
                        float pmA = xA0 + xA1, pqA = xA0*xA0 + xA1*xA1;
                        float pmB = xB0 + xB1, pqB = xB0*xB0 + xB1*xB1;
#pragma unroll
                        for (int d = 1; d < 16; d <<= 1) {
                            pmA += __shfl_xor_sync(0xffffffffu, pmA, d);
                            pqA += __shfl_xor_sync(0xffffffffu, pqA, d);
                            pmB += __shfl_xor_sync(0xffffffffu, pmB, d);
                            pqB += __shfl_xor_sync(0xffffffffu, pqB, d);
                        }
                        float muA = pmA * (1.0f / 32.0f);
                        float vaA = pqA * (1.0f / 32.0f) - muA * muA;
                        float rnA = rsqrtf(vaA + 1e-5f);
                        float muB = pmB * (1.0f / 32.0f);
                        float vaB = pqB * (1.0f / 32.0f) - muB * muB;
                        float rnB = rsqrtf(vaB + 1e-5f);
                        ov[j] = make_float4((xA0 - muA) * rnA, (xA1 - muA) * rnA,
                                            (xB0 - muB) * rnB, (xB1 - muB) * rnB);
                    }
                }
            }

            // ---- g = Xs @ Wg (own tokens, 2 col passes, packed) ----
            float4 ga[9];
            {
#pragma unroll
                for (int j = 0; j < 9; j++) ga[j] = make_float4(0, 0, 0, 0);
#pragma unroll
                for (int pass = 0; pass < 2; pass++) {
                    int cp = pass * 64 + col;
                    u64 b0[9], b1[9];
#pragma unroll
                    for (int j = 0; j < 9; j++) { b0[j] = 0ull; b1[j] = 0ull; }
#pragma unroll 2
                    for (int k2 = 0; k2 < 32; k2++) {
                        ulonglong2 wp = *(const ulonglong2*)(WPbuf + OFF_WG + L * 8192 + k2 * 256 + cp * 2);
#pragma unroll
                        for (int j = 0; j < 9; j++) {
                            int t = 2 * j + wsel;
                            if (t < 17) {
                                u64 xp = *(const u64*)(Xs + t * 68 + 2 * k2);
                                fma2(b0[j], xp, wp.x); fma2(b1[j], xp, wp.y);
                            }
                        }
                    }
#pragma unroll
                    for (int j = 0; j < 9; j++) {
                        if (2 * j + wsel < 17) {
                            if (pass == 0) { ga[j].x = hadd2(b0[j]); ga[j].y = hadd2(b1[j]); }
                            else           { ga[j].z = hadd2(b0[j]); ga[j].w = hadd2(b1[j]); }
                        }
                    }
                }
            }
            PBAR();   // all VsP reads done; Gs may overwrite

            // ---- Gs = silu(g) * ov (overlays VsP as [17][128]) ----
            {
                float* Gs = VsP;
#pragma unroll
                for (int j = 0; j < 9; j++) {
                    int t = 2 * j + wsel;
                    if (t < 17) {
                        float4 g = ga[j], o = ov[j];
                        float rA0 = g.x / (1.f + expf(-g.x)) * o.x;
                        float rA1 = g.y / (1.f + expf(-g.y)) * o.y;
                        float rB0 = g.z / (1.f + expf(-g.z)) * o.z;
                        float rB1 = g.w / (1.f + expf(-g.w)) * o.w;
                        *(float2*)(Gs + t * 128 + col)      = make_float2(rA0, rA1);
                        *(float2*)(Gs + t * 128 + 64 + col) = make_float2(rB0, rB1);
                    }
                }
            }
            PBAR();   // Gs complete

            // ---- attn out = Gs @ Wo (packed), residual ----
            {
                const float* Gs = VsP;
                u64 c0[9], c1[9];
#pragma unroll
                for (int j = 0; j < 9; j++) { c0[j] = 0ull; c1[j] = 0ull; }
#pragma unroll 2
                for (int k2 = 0; k2 < 64; k2++) {
                    ulonglong2 wp = *(const ulonglong2*)(WPbuf + OFF_WO + L * 8192 + k2 * 128 + col * 2);
#pragma unroll
                    for (int j = 0; j < 9; j++) {
                        int t = 2 * j + wsel;
                        if (t < 17) {
                            u64 gp = *(const u64*)(Gs + t * 128 + 2 * k2);
                            fma2(c0[j], gp, wp.x); fma2(c1[j], gp, wp.y);
                        }
                    }
                }
#pragma unroll
                for (int j = 0; j < 9; j++) {
                    if (2 * j + wsel < 17) { h2[j].x += hadd2(c0[j]); h2[j].y += hadd2(c1[j]); }
                }
            }

            // ---- LN2 -> Xs (own tokens) ----
            {
                float2 ls = *(const float2*)(ln2_s + L * 64 + col);
                float2 lb = *(const float2*)(ln2_b + L * 64 + col);
#pragma unroll
                for (int j = 0; j < 9; j++) {
                    int t = 2 * j + wsel;
                    if (t < 17) {
                        float s = wsum(h2[j].x + h2[j].y);
                        float q = wsum(h2[j].x * h2[j].x + h2[j].y * h2[j].y);
                        float mu = s * (1.0f / 64.0f);
                        float var = q * (1.0f / 64.0f) - mu * mu;
                        float r = rsqrtf(var + 1e-5f);
                        *(float2*)(Xs + t * 68 + col) =
                            make_float2((h2[j].x - mu) * r * ls.x + lb.x,
                                        (h2[j].y - mu) * r * ls.y + lb.y);
                    }
                }
            }
            PBAR();   // Xs complete

            // ---- FFN1: gelu(Xs @ w1 + b1) -> Gf (packed) ----
            {
                float* Gf = Qs;
                const float* pb1 = b1 + L * 12;
#pragma unroll 1
                for (int r = plane; r < 204; r += 64) {
                    int t = r / 12, jj = r - t * 12;
                    const float* pw = WPbuf + OFF_W1 + L * 768 + jj * 2;
                    u64 acc = 0ull;
#pragma unroll
                    for (int k2 = 0; k2 < 32; k2++) {
                        u64 xp = *(const u64*)(Xs + t * 68 + 2 * k2);
                        u64 wp = *(const u64*)(pw + k2 * 24);
                        fma2(acc, xp, wp);
                    }
                    float s = hadd2(acc) + pb1[jj];
                    float c = 0.7978845608028654f * (s + 0.044715f * s * s * s);
                    Gf[r] = 0.5f * s * (1.f + tanhf(c));
                }
            }
            PBAR();   // Gf complete

            // ---- h += Gf @ w2 + b2 (packed) ----
            {
                const float* Gf = Qs;
                float2 b2v = *(const float2*)(b2 + L * 64 + col);
                u64 w2x[6], w2y[6];
#pragma unroll
                for (int k2 = 0; k2 < 6; k2++) {
                    ulonglong2 wp = *(const ulonglong2*)(WPbuf + OFF_W2 + L * 768 + k2 * 128 + col * 2);
                    w2x[k2] = wp.x; w2y[k2] = wp.y;
                }
#pragma unroll
                for (int j = 0; j < 9; j++) {
                    int t = 2 * j + wsel;
                    if (t < 17) {
                        u64 ax = 0ull, ay = 0ull;
#pragma unroll
                        for (int k2 = 0; k2 < 6; k2++) {
                            u64 g2 = *(const u64*)(Gf + t * 12 + 2 * k2);
                            fma2(ax, g2, w2x[k2]); fma2(ay, g2, w2y[k2]);
                        }
                        h2[j].x += hadd2(ax) + b2v.x;
                        h2[j].y += hadd2(ay) + b2v.y;
                    }
                }
            }
            // next layer's post-LN1 PBAR orders Gf reads vs Qs overwrite
        } // layers

        // ================= final LN (token 16, warp A) + neck + head =================
        PBAR();
        if (wsel == 0) {
            float2 hv = h2[8];     // token 16
            float s = wsum(hv.x + hv.y);
            float q = wsum(hv.x * hv.x + hv.y * hv.y);
            float mu = s * (1.0f / 64.0f);
            float var = q * (1.0f / 64.0f) - mu * mu;
            float r = rsqrtf(var + 1e-5f);
            float2 ls = *(const float2*)(lnf_s + col);
            float2 lb = *(const float2*)(lnf_b + col);
            Xs[col]   = (hv.x - mu) * r * ls.x + lb.x;
            Xs[col+1] = (hv.y - mu) * r * ls.y + lb.y;
            __syncwarp();
            if (lane < 16) {
                float sv = neck_b[lane];
#pragma unroll
                for (int k = 0; k < 64; k++) sv += Xs[k] * neck_w[k * 16 + lane];
                Qs[lane] = sv;
            }
            __syncwarp();
            if (lane < 10) {
                float sv = head_b[lane];
#pragma unroll
                for (int k = 0; k < 16; k++) sv += Qs[k] * head_w[k * 10 + lane];
                out[(long)img * 10 + lane] = sv;
            }
        }
        PBAR();
    } // img loop
#undef PBAR
}

extern "C" void kernel_launch(void* const* d_in, const int* in_sizes, int n_in,
                              void* d_out, int out_size) {
    const float* x       = (const float*)d_in[0];
    const float* patch_w = (const float*)d_in[1];
    const float* patch_b = (const float*)d_in[2];
    const float* cls     = (const float*)d_in[3];
    const float* pos     = (const float*)d_in[4];
    const float* Wq      = (const float*)d_in[5];
    const float* Wk      = (const float*)d_in[6];
    const float* Wv      = (const float*)d_in[7];
    const float* Wg      = (const float*)d_in[8];
    const float* Wo      = (const float*)d_in[9];
    const float* ln1_s   = (const float*)d_in[10];
    const float* ln1_b   = (const float*)d_in[11];
    const float* w1      = (const float*)d_in[12];
    const float* b1      = (const float*)d_in[13];
    const float* w2      = (const float*)d_in[14];
    const float* b2      = (const float*)d_in[15];
    const float* ln2_s   = (const float*)d_in[16];
    const float* ln2_b   = (const float*)d_in[17];
    const float* lnf_s   = (const float*)d_in[18];
    const float* lnf_b   = (const float*)d_in[19];
    const float* neck_w  = (const float*)d_in[20];
    const float* neck_b  = (const float*)d_in[21];
    const float* head_w  = (const float*)d_in[22];
    const float* head_b  = (const float*)d_in[23];
    float* out = (float*)d_out;

    int nimg = in_sizes[0] / 3072;

    repack_kernel<<<(NPACK + 255) / 256, 256>>>(patch_w, Wq, Wk, Wv, Wg, Wo, w1, w2);

    cudaFuncSetAttribute(vit_kernel, cudaFuncAttributeMaxDynamicSharedMemorySize,
                         SMEMF * (int)sizeof(float));
    int blocks = (nimg + IPB - 1) / IPB;
    if (blocks < 1) blocks = 1;
    vit_kernel<<<blocks, 512, SMEMF * sizeof(float)>>>(
        x, patch_b, cls, pos,
        ln1_s, ln1_b, b1, b2, ln2_s, ln2_b, lnf_s, lnf_b,
        neck_w, neck_b, head_w, head_b, out, nimg);
}